// round 4
// baseline (speedup 1.0000x reference)
#include <cuda_runtime.h>

// Problem constants (fixed by setup_inputs)
#define H 512
#define T_TREES 1024
#define N0 65536

// ---------------- device scratch (no allocs allowed) ----------------
__device__ float g_S[T_TREES * H];     // pooled leaf sums  [1024, 512]
__device__ float g_WsT[H * H];         // Wsum^T
__device__ float g_WzfT[H * H];        // Wzf^T
__device__ float g_N[H * H];           // N  = M^T
__device__ float g_N2[H * H];          // N^2
__device__ float g_G[H * H];           // N^3 = (M^3)^T
__device__ float g_bsum[H];
__device__ float g_c[H];
__device__ float g_d[H];
__device__ float g_part[4 * H * H];        // split-K partials (chain gemms)
__device__ float g_partF[2 * T_TREES * H]; // split-K partials (final gemm)

// ---------------- pooling: S[t] = sum of 64 consecutive x rows ----------------
__global__ __launch_bounds__(256) void k_pool(const float4* __restrict__ x4) {
    int tid = threadIdx.x;
    int t = blockIdx.x * 2 + (tid >> 7);   // 512 blocks -> 1024 trees
    int q = tid & 127;                     // float4 column (H/4 = 128)
    const float4* p = x4 + (size_t)t * 64 * 128 + q;
    float4 s = make_float4(0.f, 0.f, 0.f, 0.f);
#pragma unroll 16
    for (int r = 0; r < 64; ++r) {
        float4 v = p[(size_t)r * 128];
        s.x += v.x; s.y += v.y; s.z += v.z; s.w += v.w;
    }
    reinterpret_cast<float4*>(g_S)[t * 128 + q] = s;
}

// ---------------- prep: Wsum^T, Wzf^T (tiled transpose), bsum ----------------
__global__ __launch_bounds__(256) void k_prep(const float* __restrict__ Wz,
                                              const float* __restrict__ bz,
                                              const float* __restrict__ Wzf) {
    __shared__ float tile[32][33];
    int b = blockIdx.x;
    int tx = threadIdx.x & 31, ty = threadIdx.x >> 5;  // 32 x 8
    if (b < 256) {
        // Wsum^T: read sum of 4 Wz slices, write transposed
        int bx = b & 15, by = b >> 4;
#pragma unroll
        for (int i = 0; i < 4; ++i) {
            int r = by * 32 + ty + i * 8;
            int c = bx * 32 + tx;
            float v = Wz[0 * H * H + r * H + c] + Wz[1 * H * H + r * H + c]
                    + Wz[2 * H * H + r * H + c] + Wz[3 * H * H + r * H + c];
            tile[ty + i * 8][tx] = v;
        }
        __syncthreads();
#pragma unroll
        for (int i = 0; i < 4; ++i)
            g_WsT[(bx * 32 + ty + i * 8) * H + by * 32 + tx] = tile[tx][ty + i * 8];
    } else if (b < 512) {
        int bb = b - 256;
        int bx = bb & 15, by = bb >> 4;
#pragma unroll
        for (int i = 0; i < 4; ++i)
            tile[ty + i * 8][tx] = Wzf[(by * 32 + ty + i * 8) * H + bx * 32 + tx];
        __syncthreads();
#pragma unroll
        for (int i = 0; i < 4; ++i)
            g_WzfT[(bx * 32 + ty + i * 8) * H + by * 32 + tx] = tile[tx][ty + i * 8];
    } else {
        int h = threadIdx.x;
#pragma unroll
        for (int i = 0; i < 2; ++i) {
            int hh = h + i * 256;
            g_bsum[hh] = bz[0 * H + hh] + bz[1 * H + hh] + bz[2 * H + hh] + bz[3 * H + hh];
        }
    }
}

// ---------------- c = 4 * (Wzf @ bsum + bzf) ----------------
__global__ __launch_bounds__(256) void k_c(const float* __restrict__ bzf) {
    int j = blockIdx.x * 256 + threadIdx.x;
    float acc = 0.f;
#pragma unroll 8
    for (int h = 0; h < H; ++h)
        acc += g_WzfT[h * H + j] * g_bsum[h];
    g_c[j] = 4.0f * (acc + bzf[j]);
}

// ---------------- d = 16 M^2 c + 4 M c + c  (via N = M^T) ----------------
__global__ __launch_bounds__(256) void k_d() {
    int j = blockIdx.x * 256 + threadIdx.x;
    float acc = 0.f;
#pragma unroll 8
    for (int h = 0; h < H; ++h) {
        float ch = g_c[h];
        acc += ch * (16.0f * g_N2[h * H + j] + 4.0f * g_N[h * H + j]);
    }
    g_d[j] = acc + g_c[j];
}

// ---------------- generic NN GEMM, deterministic split-K ----------------
// C_partial[bz] += A[M x 512] @ B[512 x 512] over k-slice bz.
// grid = (M/64, 8, SPLITK), block = 256. Tile 64x64, BK=16, 4x4 microtile,
// double-buffered SMEM with register prefetch.
__global__ __launch_bounds__(256) void k_gemm(const float* __restrict__ A,
                                              const float* __restrict__ B,
                                              float* __restrict__ Cp) {
    __shared__ float As[2][16][64];
    __shared__ float Bs[2][16][64];
    const int tid = threadIdx.x;
    const int tx = tid & 15, ty = tid >> 4;
    const int rb = blockIdx.x * 64, cb = blockIdx.y * 64;
    const int Mrows = gridDim.x * 64;
    const int kslice = H / gridDim.z;
    const int k0base = blockIdx.z * kslice;
    const int nk = kslice / 16;

    const int lar = tid >> 2, lak = (tid & 3) * 4;   // A loader: row, k-quad
    const int lbk = tid >> 4, lbc = (tid & 15) * 4;  // B loader: k-row, col-quad

    float4 ra  = *reinterpret_cast<const float4*>(&A[(size_t)(rb + lar) * H + k0base + lak]);
    float4 rb4 = *reinterpret_cast<const float4*>(&B[(size_t)(k0base + lbk) * H + cb + lbc]);
    As[0][lak + 0][lar] = ra.x; As[0][lak + 1][lar] = ra.y;
    As[0][lak + 2][lar] = ra.z; As[0][lak + 3][lar] = ra.w;
    *reinterpret_cast<float4*>(&Bs[0][lbk][lbc]) = rb4;
    __syncthreads();

    float acc[4][4];
#pragma unroll
    for (int i = 0; i < 4; ++i)
#pragma unroll
        for (int j = 0; j < 4; ++j) acc[i][j] = 0.f;

    for (int kt = 0; kt < nk; ++kt) {
        int cur = kt & 1, nxt = cur ^ 1;
        if (kt + 1 < nk) {
            int k0 = k0base + (kt + 1) * 16;
            ra  = *reinterpret_cast<const float4*>(&A[(size_t)(rb + lar) * H + k0 + lak]);
            rb4 = *reinterpret_cast<const float4*>(&B[(size_t)(k0 + lbk) * H + cb + lbc]);
        }
#pragma unroll
        for (int kk = 0; kk < 16; ++kk) {
            float4 a = *reinterpret_cast<const float4*>(&As[cur][kk][ty * 4]);
            float4 b = *reinterpret_cast<const float4*>(&Bs[cur][kk][tx * 4]);
            float aa[4] = {a.x, a.y, a.z, a.w};
            float bb[4] = {b.x, b.y, b.z, b.w};
#pragma unroll
            for (int i = 0; i < 4; ++i)
#pragma unroll
                for (int j = 0; j < 4; ++j)
                    acc[i][j] += aa[i] * bb[j];
        }
        if (kt + 1 < nk) {
            As[nxt][lak + 0][lar] = ra.x; As[nxt][lak + 1][lar] = ra.y;
            As[nxt][lak + 2][lar] = ra.z; As[nxt][lak + 3][lar] = ra.w;
            *reinterpret_cast<float4*>(&Bs[nxt][lbk][lbc]) = rb4;
        }
        __syncthreads();
    }

    float* C = Cp + (size_t)blockIdx.z * Mrows * H;
#pragma unroll
    for (int i = 0; i < 4; ++i) {
        float4 v = make_float4(acc[i][0], acc[i][1], acc[i][2], acc[i][3]);
        *reinterpret_cast<float4*>(&C[(size_t)(rb + ty * 4 + i) * H + cb + tx * 4]) = v;
    }
}

// ---------------- combine 4 split-K partials (chain gemms) ----------------
__global__ __launch_bounds__(256) void k_combine4(float* __restrict__ dst) {
    int i = blockIdx.x * 256 + threadIdx.x;     // float4 index, grid 256 -> 65536
    const float4* p = reinterpret_cast<const float4*>(g_part);
    float4 a = p[i], b = p[i + 65536], c = p[i + 131072], e = p[i + 196608];
    float4 r = make_float4(a.x + b.x + c.x + e.x, a.y + b.y + c.y + e.y,
                           a.z + b.z + c.z + e.z, a.w + b.w + c.w + e.w);
    reinterpret_cast<float4*>(dst)[i] = r;
}

// ---------------- combine 2 split-K partials + bias d (final) ----------------
__global__ __launch_bounds__(256) void k_combineF(float* __restrict__ out) {
    int i = blockIdx.x * 256 + threadIdx.x;     // float4 index, grid 512 -> 131072
    const float4* p = reinterpret_cast<const float4*>(g_partF);
    float4 a = p[i], b = p[i + 131072];
    float4 dv = reinterpret_cast<const float4*>(g_d)[i & 127];
    float4 r = make_float4(a.x + b.x + dv.x, a.y + b.y + dv.y,
                           a.z + b.z + dv.z, a.w + b.w + dv.w);
    reinterpret_cast<float4*>(out)[i] = r;
}

// ---------------- launch ----------------
extern "C" void kernel_launch(void* const* d_in, const int* in_sizes, int n_in,
                              void* d_out, int out_size) {
    const float* x   = (const float*)d_in[0];
    const float* Wz  = (const float*)d_in[1];
    const float* bz  = (const float*)d_in[2];
    const float* Wzf = (const float*)d_in[3];
    const float* bzf = (const float*)d_in[4];
    float* out = (float*)d_out;

    float *pS, *pWsT, *pWzfT, *pN, *pN2, *pG, *pPart, *pPartF;
    cudaGetSymbolAddress((void**)&pS,    g_S);
    cudaGetSymbolAddress((void**)&pWsT,  g_WsT);
    cudaGetSymbolAddress((void**)&pWzfT, g_WzfT);
    cudaGetSymbolAddress((void**)&pN,    g_N);
    cudaGetSymbolAddress((void**)&pN2,   g_N2);
    cudaGetSymbolAddress((void**)&pG,    g_G);
    cudaGetSymbolAddress((void**)&pPart, g_part);
    cudaGetSymbolAddress((void**)&pPartF, g_partF);

    // pooled leaf sums (DRAM-bound, the dominant cost)
    k_pool<<<512, 256>>>((const float4*)x);

    // Wsum^T, Wzf^T, bsum
    k_prep<<<513, 256>>>(Wz, bz, Wzf);

    // c = 4 (Wzf bsum + bzf)
    k_c<<<2, 256>>>(bzf);

    // N = Wsum^T @ Wzf^T  (= M^T)
    k_gemm<<<dim3(8, 8, 4), 256>>>(pWsT, pWzfT, pPart);
    k_combine4<<<256, 256>>>(pN);

    // N2 = N @ N
    k_gemm<<<dim3(8, 8, 4), 256>>>(pN, pN, pPart);
    k_combine4<<<256, 256>>>(pN2);

    // G = N2 @ N  (= (M^3)^T)
    k_gemm<<<dim3(8, 8, 4), 256>>>(pN2, pN, pPart);
    k_combine4<<<256, 256>>>(pG);

    // d = 16 M^2 c + 4 M c + c
    k_d<<<2, 256>>>();

    // out = S @ G + d
    k_gemm<<<dim3(16, 8, 2), 256>>>(pS, pG, pPartF);
    k_combineF<<<512, 256>>>(out);
}

// round 7
// speedup vs baseline: 1.0997x; 1.0997x over previous
#include <cuda_runtime.h>

// Problem constants (fixed by setup_inputs)
#define H 512
#define T_TREES 1024
#define N0 65536

// ---------------- device scratch (no allocs allowed) ----------------
__device__ float g_S[T_TREES * H];     // pooled leaf sums  [1024, 512]
__device__ float g_WsT[H * H];         // Wsum^T
__device__ float g_WzfT[H * H];        // Wzf^T
__device__ float g_N[H * H];           // N  = M^T
__device__ float g_N2[H * H];          // N^2
__device__ float g_SN[T_TREES * H];    // S @ N
__device__ float g_bsum[H];
__device__ float g_c[H];
__device__ float g_d[H];
__device__ float g_part[8 * H * H];          // split-K partials (chain gemms, K<=8)
__device__ float g_partF[4 * T_TREES * H];   // split-K partials (1024-row gemms, K<=4)

// ---------------- pooling: S[t] = sum of 64 consecutive x rows ----------------
__global__ __launch_bounds__(256) void k_pool(const float4* __restrict__ x4) {
    int tid = threadIdx.x;
    int t = blockIdx.x * 2 + (tid >> 7);   // 512 blocks -> 1024 trees
    int q = tid & 127;                     // float4 column (H/4 = 128)
    const float4* p = x4 + (size_t)t * 64 * 128 + q;
    float4 s = make_float4(0.f, 0.f, 0.f, 0.f);
#pragma unroll 16
    for (int r = 0; r < 64; ++r) {
        float4 v = p[(size_t)r * 128];
        s.x += v.x; s.y += v.y; s.z += v.z; s.w += v.w;
    }
    reinterpret_cast<float4*>(g_S)[t * 128 + q] = s;
}

// ---------------- prep: Wsum^T, Wzf^T (tiled transpose), bsum ----------------
__global__ __launch_bounds__(256) void k_prep(const float* __restrict__ Wz,
                                              const float* __restrict__ bz,
                                              const float* __restrict__ Wzf) {
    __shared__ float tile[32][33];
    int b = blockIdx.x;
    int tx = threadIdx.x & 31, ty = threadIdx.x >> 5;  // 32 x 8
    if (b < 256) {
        int bx = b & 15, by = b >> 4;
#pragma unroll
        for (int i = 0; i < 4; ++i) {
            int r = by * 32 + ty + i * 8;
            int c = bx * 32 + tx;
            float v = Wz[0 * H * H + r * H + c] + Wz[1 * H * H + r * H + c]
                    + Wz[2 * H * H + r * H + c] + Wz[3 * H * H + r * H + c];
            tile[ty + i * 8][tx] = v;
        }
        __syncthreads();
#pragma unroll
        for (int i = 0; i < 4; ++i)
            g_WsT[(bx * 32 + ty + i * 8) * H + by * 32 + tx] = tile[tx][ty + i * 8];
    } else if (b < 512) {
        int bb = b - 256;
        int bx = bb & 15, by = bb >> 4;
#pragma unroll
        for (int i = 0; i < 4; ++i)
            tile[ty + i * 8][tx] = Wzf[(by * 32 + ty + i * 8) * H + bx * 32 + tx];
        __syncthreads();
#pragma unroll
        for (int i = 0; i < 4; ++i)
            g_WzfT[(bx * 32 + ty + i * 8) * H + by * 32 + tx] = tile[tx][ty + i * 8];
    } else {
        int h = threadIdx.x;
#pragma unroll
        for (int i = 0; i < 2; ++i) {
            int hh = h + i * 256;
            g_bsum[hh] = bz[0 * H + hh] + bz[1 * H + hh] + bz[2 * H + hh] + bz[3 * H + hh];
        }
    }
}

// ---------------- c = 4 * (Wzf @ bsum + bzf) ----------------
__global__ __launch_bounds__(256) void k_c(const float* __restrict__ bzf) {
    int j = blockIdx.x * 256 + threadIdx.x;
    float acc = 0.f;
#pragma unroll 8
    for (int h = 0; h < H; ++h)
        acc += g_WzfT[h * H + j] * g_bsum[h];
    g_c[j] = 4.0f * (acc + bzf[j]);
}

// ---------------- d = 16 M^2 c + 4 M c + c  (via N = M^T) ----------------
__global__ __launch_bounds__(256) void k_d() {
    int j = blockIdx.x * 256 + threadIdx.x;
    float acc = 0.f;
#pragma unroll 8
    for (int h = 0; h < H; ++h) {
        float ch = g_c[h];
        acc += ch * (16.0f * g_N2[h * H + j] + 4.0f * g_N[h * H + j]);
    }
    g_d[j] = acc + g_c[j];
}

// ---------------- generic NN GEMM, deterministic split-K ----------------
// C_partial[z] = A[M x 512] @ B[512 x 512] over k-slice z.
// grid = (M/64, 8, SPLITK), block = 256. Tile 64x64, BK=16, 4x4 microtile,
// double-buffered SMEM with register prefetch.
__global__ __launch_bounds__(256) void k_gemm(const float* __restrict__ A,
                                              const float* __restrict__ B,
                                              float* __restrict__ Cp) {
    __shared__ float As[2][16][64];
    __shared__ float Bs[2][16][64];
    const int tid = threadIdx.x;
    const int tx = tid & 15, ty = tid >> 4;
    const int rb = blockIdx.x * 64, cb = blockIdx.y * 64;
    const int Mrows = gridDim.x * 64;
    const int kslice = H / gridDim.z;
    const int k0base = blockIdx.z * kslice;
    const int nk = kslice / 16;

    const int lar = tid >> 2, lak = (tid & 3) * 4;   // A loader: row, k-quad
    const int lbk = tid >> 4, lbc = (tid & 15) * 4;  // B loader: k-row, col-quad

    float4 ra  = *reinterpret_cast<const float4*>(&A[(size_t)(rb + lar) * H + k0base + lak]);
    float4 rb4 = *reinterpret_cast<const float4*>(&B[(size_t)(k0base + lbk) * H + cb + lbc]);
    As[0][lak + 0][lar] = ra.x; As[0][lak + 1][lar] = ra.y;
    As[0][lak + 2][lar] = ra.z; As[0][lak + 3][lar] = ra.w;
    *reinterpret_cast<float4*>(&Bs[0][lbk][lbc]) = rb4;
    __syncthreads();

    float acc[4][4];
#pragma unroll
    for (int i = 0; i < 4; ++i)
#pragma unroll
        for (int j = 0; j < 4; ++j) acc[i][j] = 0.f;

    for (int kt = 0; kt < nk; ++kt) {
        int cur = kt & 1, nxt = cur ^ 1;
        if (kt + 1 < nk) {
            int k0 = k0base + (kt + 1) * 16;
            ra  = *reinterpret_cast<const float4*>(&A[(size_t)(rb + lar) * H + k0 + lak]);
            rb4 = *reinterpret_cast<const float4*>(&B[(size_t)(k0 + lbk) * H + cb + lbc]);
        }
#pragma unroll
        for (int kk = 0; kk < 16; ++kk) {
            float4 a = *reinterpret_cast<const float4*>(&As[cur][kk][ty * 4]);
            float4 b = *reinterpret_cast<const float4*>(&Bs[cur][kk][tx * 4]);
            float aa[4] = {a.x, a.y, a.z, a.w};
            float bb[4] = {b.x, b.y, b.z, b.w};
#pragma unroll
            for (int i = 0; i < 4; ++i)
#pragma unroll
                for (int j = 0; j < 4; ++j)
                    acc[i][j] += aa[i] * bb[j];
        }
        if (kt + 1 < nk) {
            As[nxt][lak + 0][lar] = ra.x; As[nxt][lak + 1][lar] = ra.y;
            As[nxt][lak + 2][lar] = ra.z; As[nxt][lak + 3][lar] = ra.w;
            *reinterpret_cast<float4*>(&Bs[nxt][lbk][lbc]) = rb4;
        }
        __syncthreads();
    }

    float* C = Cp + (size_t)blockIdx.z * Mrows * H;
#pragma unroll
    for (int i = 0; i < 4; ++i) {
        float4 v = make_float4(acc[i][0], acc[i][1], acc[i][2], acc[i][3]);
        *reinterpret_cast<float4*>(&C[(size_t)(rb + ty * 4 + i) * H + cb + tx * 4]) = v;
    }
}

// ---------------- combine 8 split-K partials (chain gemms, 512x512) ----------------
__global__ __launch_bounds__(256) void k_combine8(float* __restrict__ dst) {
    int i = blockIdx.x * 256 + threadIdx.x;     // float4 index; grid 256 -> 65536
    const float4* p = reinterpret_cast<const float4*>(g_part);
    float4 r = make_float4(0.f, 0.f, 0.f, 0.f);
#pragma unroll
    for (int s = 0; s < 8; ++s) {
        float4 v = p[i + s * 65536];
        r.x += v.x; r.y += v.y; r.z += v.z; r.w += v.w;
    }
    reinterpret_cast<float4*>(dst)[i] = r;
}

// ---------------- combine 4 split-K partials (SN, 1024x512) ----------------
__global__ __launch_bounds__(256) void k_combineSN() {
    int i = blockIdx.x * 256 + threadIdx.x;     // float4 index; grid 512 -> 131072
    const float4* p = reinterpret_cast<const float4*>(g_partF);
    float4 r = make_float4(0.f, 0.f, 0.f, 0.f);
#pragma unroll
    for (int s = 0; s < 4; ++s) {
        float4 v = p[i + s * 131072];
        r.x += v.x; r.y += v.y; r.z += v.z; r.w += v.w;
    }
    reinterpret_cast<float4*>(g_SN)[i] = r;
}

// ---------------- combine 2 split-K partials + bias d (final) ----------------
__global__ __launch_bounds__(256) void k_combineF(float* __restrict__ out) {
    int i = blockIdx.x * 256 + threadIdx.x;     // float4 index; grid 512 -> 131072
    const float4* p = reinterpret_cast<const float4*>(g_partF);
    float4 a = p[i], b = p[i + 131072];
    float4 dv = reinterpret_cast<const float4*>(g_d)[i & 127];
    float4 r = make_float4(a.x + b.x + dv.x, a.y + b.y + dv.y,
                           a.z + b.z + dv.z, a.w + b.w + dv.w);
    reinterpret_cast<float4*>(out)[i] = r;
}

// ---------------- launch (multi-stream graph: fork/join via events) ----------------
extern "C" void kernel_launch(void* const* d_in, const int* in_sizes, int n_in,
                              void* d_out, int out_size) {
    const float* x   = (const float*)d_in[0];
    const float* Wz  = (const float*)d_in[1];
    const float* bz  = (const float*)d_in[2];
    const float* Wzf = (const float*)d_in[3];
    const float* bzf = (const float*)d_in[4];
    float* out = (float*)d_out;

    float *pS, *pWsT, *pWzfT, *pN, *pN2, *pSN, *pPart, *pPartF;
    cudaGetSymbolAddress((void**)&pS,     g_S);
    cudaGetSymbolAddress((void**)&pWsT,   g_WsT);
    cudaGetSymbolAddress((void**)&pWzfT,  g_WzfT);
    cudaGetSymbolAddress((void**)&pN,     g_N);
    cudaGetSymbolAddress((void**)&pN2,    g_N2);
    cudaGetSymbolAddress((void**)&pSN,    g_SN);
    cudaGetSymbolAddress((void**)&pPart,  g_part);
    cudaGetSymbolAddress((void**)&pPartF, g_partF);

    // Lazy one-time stream/event creation (host-side only; no device memory).
    static cudaStream_t sB = nullptr, sC = nullptr;
    static cudaEvent_t evFork = nullptr, evPool = nullptr, evN = nullptr,
                       evN2 = nullptr, evSN = nullptr, evD = nullptr;
    if (sB == nullptr) {
        cudaStreamCreateWithFlags(&sB, cudaStreamNonBlocking);
        cudaStreamCreateWithFlags(&sC, cudaStreamNonBlocking);
        cudaEventCreateWithFlags(&evFork, cudaEventDisableTiming);
        cudaEventCreateWithFlags(&evPool, cudaEventDisableTiming);
        cudaEventCreateWithFlags(&evN,    cudaEventDisableTiming);
        cudaEventCreateWithFlags(&evN2,   cudaEventDisableTiming);
        cudaEventCreateWithFlags(&evSN,   cudaEventDisableTiming);
        cudaEventCreateWithFlags(&evD,    cudaEventDisableTiming);
    }

    // ---- fork side streams off the capture (legacy) stream ----
    cudaEventRecord(evFork, 0);
    cudaStreamWaitEvent(sB, evFork, 0);
    cudaStreamWaitEvent(sC, evFork, 0);

    // stream B: pooled leaf sums (DRAM-bound), overlapped with weight chain
    k_pool<<<512, 256, 0, sB>>>((const float4*)x);
    cudaEventRecord(evPool, sB);

    // stream 0 (critical path): prep -> c -> N = Wsum^T @ Wzf^T
    k_prep<<<513, 256>>>(Wz, bz, Wzf);
    k_c<<<2, 256>>>(bzf);
    k_gemm<<<dim3(8, 8, 8), 256>>>(pWsT, pWzfT, pPart);
    k_combine8<<<256, 256>>>(pN);
    cudaEventRecord(evN, 0);

    // stream C: SN = S @ N (needs pool + N), overlapped with N^2
    cudaStreamWaitEvent(sC, evPool, 0);
    cudaStreamWaitEvent(sC, evN, 0);
    k_gemm<<<dim3(16, 8, 4), 256, 0, sC>>>(pS, pN, pPartF);
    k_combineSN<<<512, 256, 0, sC>>>();
    cudaEventRecord(evSN, sC);

    // stream 0: N2 = N @ N
    k_gemm<<<dim3(8, 8, 8), 256>>>(pN, pN, pPart);
    k_combine8<<<256, 256>>>(pN2);
    cudaEventRecord(evN2, 0);

    // stream B: d = 16 M^2 c + 4 M c + c (needs N, N2, c), overlapped with final GEMM
    cudaStreamWaitEvent(sB, evN2, 0);
    k_d<<<2, 256, 0, sB>>>();
    cudaEventRecord(evD, sB);

    // stream 0: out = SN @ N2 + d
    cudaStreamWaitEvent(0, evSN, 0);
    k_gemm<<<dim3(16, 8, 2), 256>>>(pSN, pN2, pPartF);
    cudaStreamWaitEvent(0, evD, 0);
    k_combineF<<<512, 256>>>(out);
}